// round 13
// baseline (speedup 1.0000x reference)
#include <cuda_runtime.h>
#include <math.h>
#include <stdint.h>

#define CHANNELS 192
#define CPARAMS  43

// Table: v range [-6.5, 6.5], step h = 1/64
#define NK      832              // 13 * 64 intervals per channel
#define OFFK    64               // 1.0 / h in knots
#define NSLOT   (NK + 3)         // 835 p-value knots per channel
#define NC      (NSLOT + OFFK)   // 899 CDF samples per channel
#define H_STEP  (1.0f / 64.0f)
#define INV_RANGE (1.0f / 13.0f)
#define UU_SCALE  831.999f       // (NK - eps): i in [0, 831]

#define GRP      32                      // channels per block table
#define NGRP     (CHANNELS / GRP)        // 6
#define NCHUNK   48                      // 6*48 = 288 blocks, all co-resident
#define NBLOCKS  (NGRP * NCHUNK)         // 288
#define MAIN_THREADS 512
#define ROWS_PER_ITER (MAIN_THREADS / GRP)   // 16
#define UB 8
#define SMEM_BYTES (NSLOT * GRP * 4)     // 106,880 B -> 2 CTAs/SM

// p values at knots, transposed per group: g_ptab[(g*NSLOT + s)*GRP + c]
__device__ float g_ptab[NGRP * NSLOT * GRP];
// monotonic arrival counter for the device-wide barrier (never reset;
// launches are stream-serialized so each launch owns one 288-ticket window)
__device__ unsigned int g_arrive;

// ---------------------------------------------------------------------------

__device__ __forceinline__ float softplus_acc(float v) {
    return fmaxf(v, 0.0f) + log1pf(expf(-fabsf(v)));
}
__device__ __forceinline__ float tanh_fast(float x) {
    x = fminf(fmaxf(x, -20.0f), 20.0f);
    float e = __expf(-2.0f * x);
    return __fdividef(1.0f - e, 1.0f + e);
}
__device__ __forceinline__ float sigmoid_fast(float x) {
    return __fdividef(1.0f, 1.0f + __expf(-x));
}

__device__ __forceinline__ float cdf_eval(float u, const float* __restrict__ K) {
    float h[3];
#pragma unroll
    for (int j = 0; j < 3; j++) {
        h[j] = fmaf(u, K[j], K[3 + j]);
        h[j] = fmaf(K[6 + j], tanh_fast(h[j]), h[j]);
    }
    float y[3];
#pragma unroll
    for (int p = 0; p < 3; p++) y[p] = K[18 + p];
#pragma unroll
    for (int i = 0; i < 3; i++)
#pragma unroll
        for (int p = 0; p < 3; p++) y[p] = fmaf(h[i], K[9 + i * 3 + p], y[p]);
#pragma unroll
    for (int j = 0; j < 3; j++) y[j] = fmaf(K[21 + j], tanh_fast(y[j]), y[j]);
    float z[3];
#pragma unroll
    for (int p = 0; p < 3; p++) z[p] = K[33 + p];
#pragma unroll
    for (int i = 0; i < 3; i++)
#pragma unroll
        for (int p = 0; p < 3; p++) z[p] = fmaf(y[i], K[24 + i * 3 + p], z[p]);
#pragma unroll
    for (int j = 0; j < 3; j++) z[j] = fmaf(K[36 + j], tanh_fast(z[j]), z[j]);
    float f = K[42];
#pragma unroll
    for (int i = 0; i < 3; i++) f = fmaf(z[i], K[39 + i], f);
    return sigmoid_fast(f);
}

// Catmull-Rom from 4 knot values
__device__ __forceinline__ float cr_eval(float fm, float f0, float f1, float f2,
                                         float tf) {
    float A = f0;
    float B = 0.5f * (f1 - fm);
    float Cc = fm - 2.5f * f0 + 2.0f * f1 - 0.5f * f2;
    float D = 0.5f * (f2 - fm) + 1.5f * (f0 - f1);
    return fmaf(tf, fmaf(tf, fmaf(tf, D, Cc), B), A);
}

// Single fused kernel. grid = (NCHUNK, NGRP), 512 threads, 2 CTAs/SM.
// Phase A: first 192 blocks build one channel's p-knot table each.
// Device-wide ticket barrier. Phase B: table to SMEM, interpolate stream.
__global__ void __launch_bounds__(MAIN_THREADS, 2)
de_fused(const float* __restrict__ xin, float* __restrict__ out, int rows,
         const float* __restrict__ a0, const float* __restrict__ a1,
         const float* __restrict__ a2,
         const float* __restrict__ b0, const float* __restrict__ b1,
         const float* __restrict__ b2, const float* __restrict__ b3,
         const float* __restrict__ H0, const float* __restrict__ H1,
         const float* __restrict__ H2, const float* __restrict__ H3) {
    extern __shared__ float s_tab[];       // [NSLOT][GRP]; scratch in phase A
    __shared__ float sk[CPARAMS];
    const int t = threadIdx.x;
    const int g = blockIdx.y;
    const int bid = blockIdx.y * NCHUNK + blockIdx.x;   // 0..287

    // ---- Phase A: table construction (blocks 0..191, one channel each) ----
    if (bid < CHANNELS) {
        const int ch = bid;
        if (t < CPARAMS) {
            float v;
            if      (t < 3)  v = softplus_acc(H0[ch * 3 + t]);
            else if (t < 6)  v = b0[ch * 3 + (t - 3)];
            else if (t < 9)  v = tanhf(a0[ch * 3 + (t - 6)]);
            else if (t < 18) v = softplus_acc(H1[ch * 9 + (t - 9)]);
            else if (t < 21) v = b1[ch * 3 + (t - 18)];
            else if (t < 24) v = tanhf(a1[ch * 3 + (t - 21)]);
            else if (t < 33) v = softplus_acc(H2[ch * 9 + (t - 24)]);
            else if (t < 36) v = b2[ch * 3 + (t - 33)];
            else if (t < 39) v = tanhf(a2[ch * 3 + (t - 36)]);
            else if (t < 42) v = softplus_acc(H3[ch * 3 + (t - 39)]);
            else             v = b3[ch];
            sk[t] = v;
        }
        __syncthreads();

        float* W = s_tab;                  // scratch alias (NC*4 = 3.6 KB)
        const float u0 = -7.0f - H_STEP;   // W[j] = cdf(u0 + j*h)
        for (int j = t; j < NC; j += MAIN_THREADS) {
            float u = fmaf((float)j, H_STEP, u0);
            W[j] = cdf_eval(u, sk);
        }
        __syncthreads();

        const int cg2 = ch & (GRP - 1);
        const int gg  = ch >> 5;
        for (int s = t; s < NSLOT; s += MAIN_THREADS)
            g_ptab[(gg * NSLOT + s) * GRP + cg2] = W[s + OFFK] - W[s];
    }

    // ---- Device-wide ticket barrier (all 288 blocks co-resident) ----
    __threadfence();
    __syncthreads();
    if (t == 0) {
        unsigned int ticket = atomicAdd(&g_arrive, 1u);
        unsigned int target = (ticket / NBLOCKS) * NBLOCKS + NBLOCKS;
        unsigned int v;
        do {
            asm volatile("ld.acquire.gpu.u32 %0, [%1];"
                         : "=r"(v) : "l"(&g_arrive) : "memory");
            if (v < target) __nanosleep(64);
        } while (v < target);
    }
    __syncthreads();

    // ---- Phase B: cp.async table fill ----
    {
        const float4* __restrict__ gsrc4 =
            reinterpret_cast<const float4*>(g_ptab + g * NSLOT * GRP);
        unsigned int sbase = (unsigned int)__cvta_generic_to_shared(s_tab);
        for (int j = t; j < (NSLOT * GRP) / 4; j += MAIN_THREADS) {
            asm volatile("cp.async.cg.shared.global [%0], [%1], 16;\n"
                         :: "r"(sbase + j * 16), "l"(gsrc4 + j) : "memory");
        }
        asm volatile("cp.async.commit_group;\n" ::: "memory");
        asm volatile("cp.async.wait_group 0;\n" ::: "memory");
    }
    __syncthreads();

    // ---- Phase B: interpolation stream ----
    const int c   = t & (GRP - 1);         // lane = channel
    const int w   = t >> 5;                // warp = row offset, 0..15
    const int col = g * GRP + c;

    const int chunk  = blockIdx.x;
    const int rbase  = rows / NCHUNK;
    const int rextra = rows - rbase * NCHUNK;
    const int r0     = chunk * rbase + min(chunk, rextra);
    const int nrows  = rbase + (chunk < rextra ? 1 : 0);
    const int r_end  = r0 + nrows;

    int r = r0 + w;
    const int nfull = nrows / (ROWS_PER_ITER * UB);

    float vbuf[UB];
    if (nfull > 0) {
#pragma unroll
        for (int u = 0; u < UB; u++)
            vbuf[u] = __ldcs(&xin[(r + u * ROWS_PER_ITER) * CHANNELS + col]);
    }

    for (int b = 0; b < nfull; b++) {
        // coords: saturate-fma clamp (2 ops)
        float uu[UB];
#pragma unroll
        for (int u = 0; u < UB; u++) {
            float q = __saturatef(fmaf(vbuf[u], INV_RANGE, 0.5f));
            uu[u] = q * UU_SCALE;
        }
        // all 32 LDS issued back-to-back
        float f[UB][4];
#pragma unroll
        for (int u = 0; u < UB; u++) {
            int base = (int)uu[u] * GRP + c;
            f[u][0] = s_tab[base];
            f[u][1] = s_tab[base + GRP];
            f[u][2] = s_tab[base + 2 * GRP];
            f[u][3] = s_tab[base + 3 * GRP];
        }
        // prefetch next x while gathers are in flight
        const int rn = r + ROWS_PER_ITER * UB;
        if (b + 1 < nfull) {
#pragma unroll
            for (int u = 0; u < UB; u++)
                vbuf[u] = __ldcs(&xin[(rn + u * ROWS_PER_ITER) * CHANNELS + col]);
        }
        // math + coalesced streaming stores
#pragma unroll
        for (int u = 0; u < UB; u++) {
            float tf = uu[u] - (float)((int)uu[u]);
            __stcs(&out[(r + u * ROWS_PER_ITER) * CHANNELS + col],
                   cr_eval(f[u][0], f[u][1], f[u][2], f[u][3], tf));
        }
        r = rn;
    }

    // remainder: staged UB=4 batches, then scalar
    while (r + 3 * ROWS_PER_ITER < r_end) {
        float uu[4];
#pragma unroll
        for (int u = 0; u < 4; u++) {
            float v = __ldcs(&xin[(r + u * ROWS_PER_ITER) * CHANNELS + col]);
            uu[u] = __saturatef(fmaf(v, INV_RANGE, 0.5f)) * UU_SCALE;
        }
        float f[4][4];
#pragma unroll
        for (int u = 0; u < 4; u++) {
            int base = (int)uu[u] * GRP + c;
            f[u][0] = s_tab[base];
            f[u][1] = s_tab[base + GRP];
            f[u][2] = s_tab[base + 2 * GRP];
            f[u][3] = s_tab[base + 3 * GRP];
        }
#pragma unroll
        for (int u = 0; u < 4; u++) {
            float tf = uu[u] - (float)((int)uu[u]);
            __stcs(&out[(r + u * ROWS_PER_ITER) * CHANNELS + col],
                   cr_eval(f[u][0], f[u][1], f[u][2], f[u][3], tf));
        }
        r += 4 * ROWS_PER_ITER;
    }
    for (; r < r_end; r += ROWS_PER_ITER) {
        float v = __ldcs(&xin[r * CHANNELS + col]);
        float uu = __saturatef(fmaf(v, INV_RANGE, 0.5f)) * UU_SCALE;
        int i = (int)uu;
        float tf = uu - (float)i;
        int base = i * GRP + c;
        __stcs(&out[r * CHANNELS + col],
               cr_eval(s_tab[base], s_tab[base + GRP],
                       s_tab[base + 2 * GRP], s_tab[base + 3 * GRP], tf));
    }
}

// ---------------------------------------------------------------------------

extern "C" void kernel_launch(void* const* d_in, const int* in_sizes, int n_in,
                              void* d_out, int out_size) {
    const float* x  = (const float*)d_in[0];
    const float* a0 = (const float*)d_in[1];
    const float* a1 = (const float*)d_in[2];
    const float* a2 = (const float*)d_in[3];
    const float* b0 = (const float*)d_in[4];
    const float* b1 = (const float*)d_in[5];
    const float* b2 = (const float*)d_in[6];
    const float* b3 = (const float*)d_in[7];
    const float* H0 = (const float*)d_in[8];
    const float* H1 = (const float*)d_in[9];
    const float* H2 = (const float*)d_in[10];
    const float* H3 = (const float*)d_in[11];
    float* out = (float*)d_out;

    int total = in_sizes[0];
    int rows  = total / CHANNELS;    // 65536

    static int smem_set = 0;
    if (!smem_set) {
        cudaFuncSetAttribute(de_fused, cudaFuncAttributeMaxDynamicSharedMemorySize,
                             SMEM_BYTES);
        smem_set = 1;
    }

    dim3 mgrid(NCHUNK, NGRP);
    de_fused<<<mgrid, MAIN_THREADS, SMEM_BYTES>>>(
        x, out, rows, a0, a1, a2, b0, b1, b2, b3, H0, H1, H2, H3);
}

// round 14
// speedup vs baseline: 1.1363x; 1.1363x over previous
#include <cuda_runtime.h>
#include <math.h>
#include <stdint.h>

#define CHANNELS 192
#define CPARAMS  43

// Table: v range [-6.5, 6.5], step h = 1/64
#define NK      832              // 13 * 64 intervals per channel
#define OFFK    64               // 1.0 / h in knots
#define NSLOT   (NK + 3)         // 835 p-value knots per channel
#define NC      (NSLOT + OFFK)   // 899 CDF samples per channel
#define H_STEP  (1.0f / 64.0f)
#define INV_RANGE (1.0f / 13.0f)
#define UU_SCALE  831.999f       // i lands in [0, 831]

#define GRP      32                      // channels per main-kernel block
#define NGRP     (CHANNELS / GRP)        // 6
#define NCHUNK   48                      // 6*48 = 288 blocks = 2 CTA/SM
#define MAIN_THREADS 512
#define ROWS_PER_ITER (MAIN_THREADS / GRP)   // 16
#define UB 8
#define SMEM_BYTES (NSLOT * GRP * 4)     // 106,880 B -> 2 CTAs/SM

#define PREP_THREADS 512

// p values at knots, transposed per group: g_ptab[(g*NSLOT + s)*GRP + c]
__device__ float g_ptab[NGRP * NSLOT * GRP];

// ---------------------------------------------------------------------------

__device__ __forceinline__ float softplus_acc(float v) {
    return fmaxf(v, 0.0f) + log1pf(expf(-fabsf(v)));
}
__device__ __forceinline__ float tanh_fast(float x) {
    x = fminf(fmaxf(x, -20.0f), 20.0f);
    float e = __expf(-2.0f * x);
    return __fdividef(1.0f - e, 1.0f + e);
}
__device__ __forceinline__ float sigmoid_fast(float x) {
    return __fdividef(1.0f, 1.0f + __expf(-x));
}

__device__ __forceinline__ float cdf_eval(float u, const float* __restrict__ K) {
    float h[3];
#pragma unroll
    for (int j = 0; j < 3; j++) {
        h[j] = fmaf(u, K[j], K[3 + j]);
        h[j] = fmaf(K[6 + j], tanh_fast(h[j]), h[j]);
    }
    float y[3];
#pragma unroll
    for (int p = 0; p < 3; p++) y[p] = K[18 + p];
#pragma unroll
    for (int i = 0; i < 3; i++)
#pragma unroll
        for (int p = 0; p < 3; p++) y[p] = fmaf(h[i], K[9 + i * 3 + p], y[p]);
#pragma unroll
    for (int j = 0; j < 3; j++) y[j] = fmaf(K[21 + j], tanh_fast(y[j]), y[j]);
    float z[3];
#pragma unroll
    for (int p = 0; p < 3; p++) z[p] = K[33 + p];
#pragma unroll
    for (int i = 0; i < 3; i++)
#pragma unroll
        for (int p = 0; p < 3; p++) z[p] = fmaf(y[i], K[24 + i * 3 + p], z[p]);
#pragma unroll
    for (int j = 0; j < 3; j++) z[j] = fmaf(K[36 + j], tanh_fast(z[j]), z[j]);
    float f = K[42];
#pragma unroll
    for (int i = 0; i < 3; i++) f = fmaf(z[i], K[39 + i], f);
    return sigmoid_fast(f);
}

// Prep: one block per channel (192 blocks x 512 threads, 2 evals/thread).
// Signals dependent launch as soon as its table slice is globally visible.
__global__ void __launch_bounds__(PREP_THREADS)
de_prep(const float* __restrict__ a0, const float* __restrict__ a1,
        const float* __restrict__ a2,
        const float* __restrict__ b0, const float* __restrict__ b1,
        const float* __restrict__ b2, const float* __restrict__ b3,
        const float* __restrict__ H0, const float* __restrict__ H1,
        const float* __restrict__ H2, const float* __restrict__ H3) {
    __shared__ float sk[CPARAMS];
    __shared__ float W[NC];
    const int ch = blockIdx.x;
    const int t = threadIdx.x;

    if (t < CPARAMS) {
        float v;
        if      (t < 3)  v = softplus_acc(H0[ch * 3 + t]);
        else if (t < 6)  v = b0[ch * 3 + (t - 3)];
        else if (t < 9)  v = tanhf(a0[ch * 3 + (t - 6)]);
        else if (t < 18) v = softplus_acc(H1[ch * 9 + (t - 9)]);
        else if (t < 21) v = b1[ch * 3 + (t - 18)];
        else if (t < 24) v = tanhf(a1[ch * 3 + (t - 21)]);
        else if (t < 33) v = softplus_acc(H2[ch * 9 + (t - 24)]);
        else if (t < 36) v = b2[ch * 3 + (t - 33)];
        else if (t < 39) v = tanhf(a2[ch * 3 + (t - 36)]);
        else if (t < 42) v = softplus_acc(H3[ch * 3 + (t - 39)]);
        else             v = b3[ch];
        sk[t] = v;
    }
    __syncthreads();

    const float u0 = -7.0f - H_STEP;     // W[j] = cdf(u0 + j*h)
#pragma unroll
    for (int j = t; j < NC; j += PREP_THREADS) {
        float u = fmaf((float)j, H_STEP, u0);
        W[j] = cdf_eval(u, sk);
    }
    __syncthreads();

    const int gg  = ch >> 5;
    const int cg  = ch & (GRP - 1);
    for (int s = t; s < NSLOT; s += PREP_THREADS)
        g_ptab[(gg * NSLOT + s) * GRP + cg] = W[s + OFFK] - W[s];

    __threadfence();
    __syncthreads();
    // allow the dependent main kernel's post-wait section to proceed
    asm volatile("griddepcontrol.launch_dependents;" ::: "memory");
}

// Catmull-Rom from 4 knot values
__device__ __forceinline__ float cr_eval(float fm, float f0, float f1, float f2,
                                         float tf) {
    float A = f0;
    float B = 0.5f * (f1 - fm);
    float Cc = fm - 2.5f * f0 + 2.0f * f1 - 0.5f * f2;
    float D = 0.5f * (f2 - fm) + 1.5f * (f0 - f1);
    return fmaf(tf, fmaf(tf, fmaf(tf, D, Cc), B), A);
}

// Main (PDL secondary): prefetch x first (independent of table), then
// griddepcontrol.wait, then cp.async table fill and the staged pipeline.
__global__ void __launch_bounds__(MAIN_THREADS, 2)
de_main(const float* __restrict__ xin, float* __restrict__ out, int rows) {
    extern __shared__ float s_tab[];       // [NSLOT][GRP]
    const int t = threadIdx.x;
    const int g = blockIdx.y;

    const int c   = t & (GRP - 1);         // lane = channel
    const int w   = t >> 5;                // warp = row offset, 0..15
    const int col = g * GRP + c;

    const int chunk  = blockIdx.x;
    const int rbase  = rows / NCHUNK;
    const int rextra = rows - rbase * NCHUNK;
    const int r0     = chunk * rbase + min(chunk, rextra);
    const int nrows  = rbase + (chunk < rextra ? 1 : 0);
    const int r_end  = r0 + nrows;

    int r = r0 + w;
    const int nfull = nrows / (ROWS_PER_ITER * UB);

    // ---- pre-wait: issue first-iteration x loads (independent of g_ptab) ----
    float vbuf[UB];
    if (nfull > 0) {
#pragma unroll
        for (int u = 0; u < UB; u++)
            vbuf[u] = __ldcs(&xin[(r + u * ROWS_PER_ITER) * CHANNELS + col]);
    }

    // ---- wait for prep's table writes ----
    asm volatile("griddepcontrol.wait;" ::: "memory");

    // ---- cp.async table fill ----
    {
        const float4* __restrict__ gsrc4 =
            reinterpret_cast<const float4*>(g_ptab + g * NSLOT * GRP);
        unsigned int sbase = (unsigned int)__cvta_generic_to_shared(s_tab);
        for (int j = t; j < (NSLOT * GRP) / 4; j += MAIN_THREADS) {
            asm volatile("cp.async.cg.shared.global [%0], [%1], 16;\n"
                         :: "r"(sbase + j * 16), "l"(gsrc4 + j) : "memory");
        }
        asm volatile("cp.async.commit_group;\n" ::: "memory");
        asm volatile("cp.async.wait_group 0;\n" ::: "memory");
    }
    __syncthreads();

    for (int b = 0; b < nfull; b++) {
        // coords: saturating-fma clamp
        float uu[UB];
#pragma unroll
        for (int u = 0; u < UB; u++) {
            float q = __saturatef(fmaf(vbuf[u], INV_RANGE, 0.5f));
            uu[u] = q * UU_SCALE;
        }
        // all 32 LDS issued back-to-back
        float f[UB][4];
#pragma unroll
        for (int u = 0; u < UB; u++) {
            int base = (int)uu[u] * GRP + c;
            f[u][0] = s_tab[base];
            f[u][1] = s_tab[base + GRP];
            f[u][2] = s_tab[base + 2 * GRP];
            f[u][3] = s_tab[base + 3 * GRP];
        }
        // prefetch next x while gathers are in flight
        const int rn = r + ROWS_PER_ITER * UB;
        if (b + 1 < nfull) {
#pragma unroll
            for (int u = 0; u < UB; u++)
                vbuf[u] = __ldcs(&xin[(rn + u * ROWS_PER_ITER) * CHANNELS + col]);
        }
        // math + coalesced streaming stores
#pragma unroll
        for (int u = 0; u < UB; u++) {
            float tf = uu[u] - (float)((int)uu[u]);
            __stcs(&out[(r + u * ROWS_PER_ITER) * CHANNELS + col],
                   cr_eval(f[u][0], f[u][1], f[u][2], f[u][3], tf));
        }
        r = rn;
    }

    // remainder: staged UB=4 batches, then scalar
    while (r + 3 * ROWS_PER_ITER < r_end) {
        float uu[4];
#pragma unroll
        for (int u = 0; u < 4; u++) {
            float v = __ldcs(&xin[(r + u * ROWS_PER_ITER) * CHANNELS + col]);
            uu[u] = __saturatef(fmaf(v, INV_RANGE, 0.5f)) * UU_SCALE;
        }
        float f[4][4];
#pragma unroll
        for (int u = 0; u < 4; u++) {
            int base = (int)uu[u] * GRP + c;
            f[u][0] = s_tab[base];
            f[u][1] = s_tab[base + GRP];
            f[u][2] = s_tab[base + 2 * GRP];
            f[u][3] = s_tab[base + 3 * GRP];
        }
#pragma unroll
        for (int u = 0; u < 4; u++) {
            float tf = uu[u] - (float)((int)uu[u]);
            __stcs(&out[(r + u * ROWS_PER_ITER) * CHANNELS + col],
                   cr_eval(f[u][0], f[u][1], f[u][2], f[u][3], tf));
        }
        r += 4 * ROWS_PER_ITER;
    }
    for (; r < r_end; r += ROWS_PER_ITER) {
        float v = __ldcs(&xin[r * CHANNELS + col]);
        float uu = __saturatef(fmaf(v, INV_RANGE, 0.5f)) * UU_SCALE;
        int i = (int)uu;
        float tf = uu - (float)i;
        int base = i * GRP + c;
        __stcs(&out[r * CHANNELS + col],
               cr_eval(s_tab[base], s_tab[base + GRP],
                       s_tab[base + 2 * GRP], s_tab[base + 3 * GRP], tf));
    }
}

// ---------------------------------------------------------------------------

extern "C" void kernel_launch(void* const* d_in, const int* in_sizes, int n_in,
                              void* d_out, int out_size) {
    const float* x  = (const float*)d_in[0];
    const float* a0 = (const float*)d_in[1];
    const float* a1 = (const float*)d_in[2];
    const float* a2 = (const float*)d_in[3];
    const float* b0 = (const float*)d_in[4];
    const float* b1 = (const float*)d_in[5];
    const float* b2 = (const float*)d_in[6];
    const float* b3 = (const float*)d_in[7];
    const float* H0 = (const float*)d_in[8];
    const float* H1 = (const float*)d_in[9];
    const float* H2 = (const float*)d_in[10];
    const float* H3 = (const float*)d_in[11];
    float* out = (float*)d_out;

    int total = in_sizes[0];
    int rows  = total / CHANNELS;    // 65536

    static int smem_set = 0;
    if (!smem_set) {
        cudaFuncSetAttribute(de_main, cudaFuncAttributeMaxDynamicSharedMemorySize,
                             SMEM_BYTES);
        smem_set = 1;
    }

    // primary: prep (one block per channel)
    de_prep<<<CHANNELS, PREP_THREADS>>>(a0, a1, a2, b0, b1, b2, b3,
                                        H0, H1, H2, H3);

    // secondary: main, launched with programmatic stream serialization so its
    // pre-wait section (x prefetch) overlaps prep.
    cudaLaunchConfig_t cfg = {};
    cfg.gridDim  = dim3(NCHUNK, NGRP, 1);
    cfg.blockDim = dim3(MAIN_THREADS, 1, 1);
    cfg.dynamicSmemBytes = SMEM_BYTES;
    cudaLaunchAttribute attrs[1];
    attrs[0].id = cudaLaunchAttributeProgrammaticStreamSerialization;
    attrs[0].val.programmaticStreamSerializationAllowed = 1;
    cfg.attrs = attrs;
    cfg.numAttrs = 1;
    cudaLaunchKernelEx(&cfg, de_main, x, out, rows);
}